// round 10
// baseline (speedup 1.0000x reference)
#include <cuda_runtime.h>
#include <cuda_fp16.h>
#include <cstdint>

// ============================================================
// Typed relational GCN, sm_103 baseline PTX (no tcgen05 allowed).
//   out = sum_k (adj==k) @ (V@w_k) + bias,  N=8192, F=256, fp32.
//
// R9: warp tile M32 x N32 @ 512 threads/CTA (16 warps, 4/SMSP):
//   - acc 32 regs -> fits 128-reg cap -> occupancy 2x (latency hiding)
//   - LDS:HMMA = 1:4 -> crossbar strictly subordinate to tensor
//   - CTA M256 x N64, grid 32x4; R6 single-barrier cp.async pipeline
//   - PRMT one-hot fp16 masks (validated bit-exact)
// ============================================================

#define NROWS 8192
#define FEAT  256
#define NCHUNKS 128                           // K chunks of 64
#define STAGES 4
#define STAGE_BYTES (3 * 8 * 2 * 32 * 16)     // [type][nt][half][lane][16B] = 24576
#define SMEM_TOTAL (STAGES * STAGE_BYTES)     // 98304

// B scratch, fragment-major fp16:
// [type(3)][ntile(32)][kchunk(128)][half(2)][lane(32)][16B] = 12.58 MB
__device__ __align__(256) uint8_t g_B[3u * 32u * 128u * 2u * 32u * 16u];

#define BS_HALF   512u
#define BS_CHUNK  1024u
#define BS_NTILE  131072u
#define BS_TYPE   4194304u

// ---------------- helpers ---------------------------------------------------

__device__ __forceinline__ uint32_t smem_u32(const void* p) {
    uint32_t a;
    asm("{ .reg .u64 t; cvta.to.shared.u64 t, %1; cvt.u32.u64 %0, t; }" : "=r"(a) : "l"(p));
    return a;
}

__device__ __forceinline__ uint32_t prmt(uint32_t a, uint32_t b, uint32_t sel) {
    uint32_t r;
    asm("prmt.b32 %0, %1, %2, %3;" : "=r"(r) : "r"(a), "r"(b), "r"(sel));
    return r;
}

// pack low bytes of 4 int32 (values 0..3) into one 4-byte word
__device__ __forceinline__ uint32_t pack4(int a, int b, int c, int d) {
    uint32_t x, y, r;
    asm("prmt.b32 %0, %1, %2, 0x40;"   : "=r"(x) : "r"(a), "r"(b));
    asm("prmt.b32 %0, %1, %2, 0x40;"   : "=r"(y) : "r"(c), "r"(d));
    asm("prmt.b32 %0, %1, %2, 0x5410;" : "=r"(r) : "r"(x), "r"(y));
    return r;
}

__device__ __forceinline__ void mma_f16(float* c,
                                        uint32_t a0, uint32_t a1, uint32_t a2, uint32_t a3,
                                        uint32_t b0, uint32_t b1) {
    asm volatile(
        "mma.sync.aligned.m16n8k16.row.col.f32.f16.f16.f32 "
        "{%0,%1,%2,%3}, {%4,%5,%6,%7}, {%8,%9}, {%0,%1,%2,%3};"
        : "+f"(c[0]), "+f"(c[1]), "+f"(c[2]), "+f"(c[3])
        : "r"(a0), "r"(a1), "r"(a2), "r"(a3), "r"(b0), "r"(b1));
}

__device__ __forceinline__ void cp_async16(uint32_t smem_addr, const void* gptr) {
    asm volatile("cp.async.cg.shared.global [%0], [%1], 16;"
                 :: "r"(smem_addr), "l"(gptr) : "memory");
}
#define CP_COMMIT() asm volatile("cp.async.commit_group;" ::: "memory")
#define CP_WAIT2()  asm volatile("cp.async.wait_group 2;" ::: "memory")
#define CP_WAIT0()  asm volatile("cp.async.wait_group 0;" ::: "memory")

__device__ __forceinline__ uint4 lds128(uint32_t addr) {
    uint4 v;
    asm volatile("ld.shared.v4.u32 {%0,%1,%2,%3}, [%4];"
                 : "=r"(v.x), "=r"(v.y), "=r"(v.z), "=r"(v.w) : "r"(addr));
    return v;
}

// ---------------- Stage 1: H_k = V @ w_k -> fp16 fragment-major -------------
// grid (128 j-tiles, 4 n-tiles, 3 types), block (16,16).

__global__ void stage1_kernel(const float* __restrict__ V,
                              const float* __restrict__ w1,
                              const float* __restrict__ w2,
                              const float* __restrict__ w3) {
    const int j0 = blockIdx.x * 64;
    const int n0 = blockIdx.y * 64;
    const int type = blockIdx.z;
    const float* w = (type == 0) ? w1 : (type == 1) ? w2 : w3;

    __shared__ float Vs[16][68];
    __shared__ float Ws[16][68];
    __shared__ float Ts[64][65];           // [n][j]

    const int tx = threadIdx.x, ty = threadIdx.y;
    const int t = ty * 16 + tx;

    float acc[4][4];
#pragma unroll
    for (int i = 0; i < 4; i++)
#pragma unroll
        for (int j = 0; j < 4; j++) acc[i][j] = 0.f;

    const int vrow = t >> 2, vci = (t & 3) * 4;
    const int wc = t >> 4, wn = (t & 15) * 4;

    for (int ks = 0; ks < 16; ks++) {
        float4 v = *(const float4*)&V[(size_t)(j0 + vrow) * 256 + ks * 16 + vci];
        Vs[vci + 0][vrow] = v.x; Vs[vci + 1][vrow] = v.y;
        Vs[vci + 2][vrow] = v.z; Vs[vci + 3][vrow] = v.w;
        *(float4*)&Ws[wc][wn] = *(const float4*)&w[(size_t)(ks * 16 + wc) * 256 + n0 + wn];
        __syncthreads();
#pragma unroll
        for (int c = 0; c < 16; c++) {
            float4 rv = *(const float4*)&Vs[c][ty * 4];
            float4 rw = *(const float4*)&Ws[c][tx * 4];
            float a[4] = {rv.x, rv.y, rv.z, rv.w};
            float b[4] = {rw.x, rw.y, rw.z, rw.w};
#pragma unroll
            for (int i = 0; i < 4; i++)
#pragma unroll
                for (int j = 0; j < 4; j++) acc[i][j] += a[i] * b[j];
        }
        __syncthreads();
    }
#pragma unroll
    for (int i = 0; i < 4; i++)
#pragma unroll
        for (int j = 0; j < 4; j++) Ts[tx * 4 + j][ty * 4 + i] = acc[i][j];
    __syncthreads();

    // fragment-major fp16 write.
    const int nl = t >> 2;
    const int s = t & 3;
    const int jb = s * 16;
    const int n = n0 + nl;
    const int nt = n >> 3;
    const int kc = blockIdx.x;

#pragma unroll
    for (int c = 0; c < 4; c++) {
        __half2 p01 = __floats2half2_rn(Ts[nl][jb + 2 * c], Ts[nl][jb + 2 * c + 1]);
        __half2 p89 = __floats2half2_rn(Ts[nl][jb + 2 * c + 8], Ts[nl][jb + 2 * c + 9]);
        uint2 val = make_uint2(*reinterpret_cast<uint32_t*>(&p01),
                               *reinterpret_cast<uint32_t*>(&p89));
        const int lane = 4 * (n & 7) + c;
        size_t off = (size_t)type * BS_TYPE + (size_t)nt * BS_NTILE + (size_t)kc * BS_CHUNK
                   + (size_t)(s >> 1) * BS_HALF + (size_t)lane * 16 + (size_t)(s & 1) * 8;
        *(uint2*)&g_B[off] = val;
    }
}

// ---------------- Stage 2: mask-GEMM, warp M32 x N32, 512 thr ---------------
// grid 128: bid -> (m_tile = bid>>2 of 256 rows, n_q = bid&3 of 64 feats).
// 16 warps: mslot = wid>>1 (rows i0+mslot*32..+31), nh = wid&1 (feats nh*32..+31).

__global__ void __launch_bounds__(512, 1)
stage2_kernel(const int* __restrict__ adj,
              const float* __restrict__ bias,
              float* __restrict__ out) {
    extern __shared__ uint8_t smem[];
    const uint32_t smem_base = smem_u32(smem);

    const int tid = threadIdx.x;
    const int wid = tid >> 5, l = tid & 31;
    const int mslot = wid >> 1, nh = wid & 1;
    const int m_tile = blockIdx.x >> 2;
    const int n_q = blockIdx.x & 3;
    const int i0 = m_tile * 256;
    const int li = l & 3;

    const int r0 = i0 + mslot * 32 + (l >> 2);
    const int2* a2 = (const int2*)(adj + (size_t)r0 * NROWS);

    float acc[2][4][4];
#pragma unroll
    for (int m = 0; m < 2; m++)
#pragma unroll
        for (int j = 0; j < 4; j++)
#pragma unroll
            for (int r = 0; r < 4; r++) acc[m][j][r] = 0.f;

    // prologue: stage chunks 0..2 (1536 x 16B per chunk, 3 per thread)
#pragma unroll
    for (int p = 0; p < STAGES - 1; p++) {
#pragma unroll
        for (int q = 0; q < 3; q++) {
            int idx = tid + 512 * q;                 // 0..1535
            int type = idx >> 9;
            int rem = idx & 511;
            int nt = rem >> 6;
            int hl = (rem >> 5) & 1;
            int lane = rem & 31;
            const uint8_t* src = g_B + (size_t)type * BS_TYPE
                + (size_t)(n_q * 8 + nt) * BS_NTILE + (size_t)p * BS_CHUNK
                + (size_t)hl * BS_HALF + (size_t)lane * 16;
            cp_async16(smem_base + p * STAGE_BYTES + idx * 16, src);
        }
        CP_COMMIT();
    }

    for (int c = 0; c < NCHUNKS; c++) {
        // chunk c staged (last group issued was c+2 -> wait_group 2 drains c)
        CP_WAIT2();
        __syncthreads();   // c visible; all warps done reading buffer (c-1)&3

        // stage chunk c+3 into freed buffer
        if (c + STAGES - 1 < NCHUNKS) {
            const int p = c + STAGES - 1;
#pragma unroll
            for (int q = 0; q < 3; q++) {
                int idx = tid + 512 * q;
                int type = idx >> 9;
                int rem = idx & 511;
                int nt = rem >> 6;
                int hl = (rem >> 5) & 1;
                int lane = rem & 31;
                const uint8_t* src = g_B + (size_t)type * BS_TYPE
                    + (size_t)(n_q * 8 + nt) * BS_NTILE + (size_t)p * BS_CHUNK
                    + (size_t)hl * BS_HALF + (size_t)lane * 16;
                cp_async16(smem_base + (p & 3) * STAGE_BYTES + idx * 16, src);
            }
        }
        CP_COMMIT();

        // load + pack adj chunk c (L2-latency bubble covered by sibling warps)
        uint32_t pk[2][2][4];
#pragma unroll
        for (int m = 0; m < 2; m++)
#pragma unroll
            for (int ab = 0; ab < 2; ab++) {
                const int2* ar = a2 + (size_t)(16 * m + 8 * ab) * (NROWS / 2)
                                    + (size_t)c * 32;
#pragma unroll
                for (int s = 0; s < 4; s++) {
                    int2 x0 = ar[8 * s + li];
                    int2 x1 = ar[8 * s + li + 4];
                    pk[m][ab][s] = pack4(x0.x, x0.y, x1.x, x1.y);
                }
            }

        const uint32_t sb = smem_base + (c & 3) * STAGE_BYTES;
#pragma unroll
        for (int t = 0; t < 3; t++) {
            // PRMT one-hot fp16 A fragments: both m-tiles, all 4 ksteps
            const uint32_t cmp = 0x01010101u * (t + 1);
            uint32_t am[2][4][4];
#pragma unroll
            for (int m = 0; m < 2; m++)
#pragma unroll
                for (int s = 0; s < 4; s++) {
                    uint32_t eA = __vcmpeq4(pk[m][0][s], cmp) & 0x3C3C3C3Cu;
                    uint32_t eB = __vcmpeq4(pk[m][1][s], cmp) & 0x3C3C3C3Cu;
                    am[m][s][0] = prmt(eA, 0u, 0x1404u);
                    am[m][s][1] = prmt(eB, 0u, 0x1404u);
                    am[m][s][2] = prmt(eA, 0u, 0x3424u);
                    am[m][s][3] = prmt(eB, 0u, 0x3424u);
                }
            // nt pairs: load 4 B frags (regs), then 16 MMAs, s-outer
#pragma unroll
            for (int j2 = 0; j2 < 2; j2++) {
                uint4 ub[2][2];
#pragma unroll
                for (int jj = 0; jj < 2; jj++) {
                    const int nt_l = nh * 4 + j2 * 2 + jj;
                    const uint32_t base = sb + (uint32_t)(((t * 8 + nt_l) * 2) * 512 + l * 16);
                    ub[jj][0] = lds128(base);
                    ub[jj][1] = lds128(base + 512);
                }
#pragma unroll
                for (int s = 0; s < 4; s++) {
#pragma unroll
                    for (int jj = 0; jj < 2; jj++) {
                        const uint32_t b0 = (s & 1) ? ub[jj][s >> 1].z : ub[jj][s >> 1].x;
                        const uint32_t b1 = (s & 1) ? ub[jj][s >> 1].w : ub[jj][s >> 1].y;
#pragma unroll
                        for (int m = 0; m < 2; m++)
                            mma_f16(acc[m][j2 * 2 + jj],
                                    am[m][s][0], am[m][s][1], am[m][s][2], am[m][s][3],
                                    b0, b1);
                    }
                }
            }
        }
    }

    CP_WAIT0();

    // epilogue: out = acc + bias
#pragma unroll
    for (int m = 0; m < 2; m++) {
        const int rowA = r0 + 16 * m;
#pragma unroll
        for (int j = 0; j < 4; j++) {
            int col = n_q * 64 + nh * 32 + j * 8 + 2 * li;
            float b0 = __ldg(&bias[col]);
            float b1 = __ldg(&bias[col + 1]);
            float2 w0 = make_float2(acc[m][j][0] + b0, acc[m][j][1] + b1);
            float2 w1 = make_float2(acc[m][j][2] + b0, acc[m][j][3] + b1);
            *(float2*)&out[(size_t)rowA * FEAT + col] = w0;
            *(float2*)&out[(size_t)(rowA + 8) * FEAT + col] = w1;
        }
    }
}

// ---------------- launch ---------------------------------------------------

extern "C" void kernel_launch(void* const* d_in, const int* in_sizes, int n_in,
                              void* d_out, int out_size) {
    const float* V    = (const float*)d_in[0];
    const int*   adj  = (const int*)d_in[1];
    const float* w1   = (const float*)d_in[2];
    const float* w2   = (const float*)d_in[3];
    const float* w3   = (const float*)d_in[4];
    const float* bias = (const float*)d_in[5];
    float* out = (float*)d_out;

    cudaFuncSetAttribute(stage2_kernel,
                         cudaFuncAttributeMaxDynamicSharedMemorySize, SMEM_TOTAL);

    stage1_kernel<<<dim3(128, 4, 3), dim3(16, 16)>>>(V, w1, w2, w3);
    stage2_kernel<<<128, 512, SMEM_TOTAL>>>(adj, bias, out);
}

// round 11
// speedup vs baseline: 1.4209x; 1.4209x over previous
#include <cuda_runtime.h>
#include <cuda_fp16.h>
#include <cstdint>

// ============================================================
// Typed relational GCN, sm_103 baseline PTX (no tcgen05 allowed).
//   out = sum_k (adj==k) @ (V@w_k) + bias,  N=8192, F=256, fp32.
//
// R10: stage2 = exact R4 config (M16 x N128, 354 us measured) with
// bit-exact PRMT masks. stage1 rewritten on HMMA (was fp32-FFMA
// roofline-bound at ~95 us): V cvt fp16 in-flight, w fragments in
// smem, fp32 accum, epilogue writes g_B fragment layout directly.
// ============================================================

#define NROWS 8192
#define FEAT  256
#define NCHUNKS 128                           // K chunks of 64
#define STAGES 4
#define STAGE_BYTES (3 * 16 * 2 * 32 * 16)    // [type][nt][half][lane][16B] = 49152
#define SMEM_TOTAL (STAGES * STAGE_BYTES)     // 196608

// B scratch, fragment-major fp16:
// [type(3)][ntile(32)][kchunk(128)][half(2)][lane(32)][16B] = 12.58 MB
__device__ __align__(256) uint8_t g_B[3u * 32u * 128u * 2u * 32u * 16u];

#define BS_HALF   512u
#define BS_CHUNK  1024u
#define BS_NTILE  131072u
#define BS_TYPE   4194304u

// stage1 smem: w fragments + 4 warp transpose buffers
#define S1_WFRAG_BYTES (16 * 8 * 32 * 8)      // [ks][nt][lane][2 words] = 32768
#define S1_TBUF_BYTES  (32 * 66 * 2)          // [j32][n64 pad 66] half = 4224
#define S1_SMEM (S1_WFRAG_BYTES + 4 * S1_TBUF_BYTES)   // 49664

// ---------------- helpers ---------------------------------------------------

__device__ __forceinline__ uint32_t smem_u32(const void* p) {
    uint32_t a;
    asm("{ .reg .u64 t; cvta.to.shared.u64 t, %1; cvt.u32.u64 %0, t; }" : "=r"(a) : "l"(p));
    return a;
}

__device__ __forceinline__ uint32_t prmt(uint32_t a, uint32_t b, uint32_t sel) {
    uint32_t r;
    asm("prmt.b32 %0, %1, %2, %3;" : "=r"(r) : "r"(a), "r"(b), "r"(sel));
    return r;
}

__device__ __forceinline__ uint32_t pack4(int a, int b, int c, int d) {
    uint32_t x, y, r;
    asm("prmt.b32 %0, %1, %2, 0x40;"   : "=r"(x) : "r"(a), "r"(b));
    asm("prmt.b32 %0, %1, %2, 0x40;"   : "=r"(y) : "r"(c), "r"(d));
    asm("prmt.b32 %0, %1, %2, 0x5410;" : "=r"(r) : "r"(x), "r"(y));
    return r;
}

__device__ __forceinline__ uint32_t f2h2(float a, float b) {
    __half2 h = __floats2half2_rn(a, b);      // .x = a (low half)
    return *reinterpret_cast<uint32_t*>(&h);
}

__device__ __forceinline__ void mma_f16(float* c,
                                        uint32_t a0, uint32_t a1, uint32_t a2, uint32_t a3,
                                        uint32_t b0, uint32_t b1) {
    asm volatile(
        "mma.sync.aligned.m16n8k16.row.col.f32.f16.f16.f32 "
        "{%0,%1,%2,%3}, {%4,%5,%6,%7}, {%8,%9}, {%0,%1,%2,%3};"
        : "+f"(c[0]), "+f"(c[1]), "+f"(c[2]), "+f"(c[3])
        : "r"(a0), "r"(a1), "r"(a2), "r"(a3), "r"(b0), "r"(b1));
}

__device__ __forceinline__ void cp_async16(uint32_t smem_addr, const void* gptr) {
    asm volatile("cp.async.cg.shared.global [%0], [%1], 16;"
                 :: "r"(smem_addr), "l"(gptr) : "memory");
}
#define CP_COMMIT() asm volatile("cp.async.commit_group;" ::: "memory")
#define CP_WAIT3()  asm volatile("cp.async.wait_group 3;" ::: "memory")
#define CP_WAIT0()  asm volatile("cp.async.wait_group 0;" ::: "memory")

// ---------------- Stage 1: H_k = V @ w_k on HMMA ---------------------------
// grid (64 j-tiles of 128, 4 n-quarters, 3 types), block 128 (4 warps).
// Warp wid: rows [j0 + 32*wid, +32), feats [n0, n0+64). fp32 accumulate.

__global__ void __launch_bounds__(128)
stage1_kernel(const float* __restrict__ V,
              const float* __restrict__ w1,
              const float* __restrict__ w2,
              const float* __restrict__ w3) {
    extern __shared__ uint8_t s1mem[];
    const int j0 = blockIdx.x * 128;
    const int n0 = blockIdx.y * 64;
    const int type = blockIdx.z;
    const float* w = (type == 0) ? w1 : (type == 1) ? w2 : w3;

    const int tid = threadIdx.x;
    const int wid = tid >> 5, l = tid & 31;
    const int li = l & 3, lr = l >> 2;

    // ---- build w fragments (stage2-proven B layout) ----
    // wfrag[(ks*8+nt)*32 + lane] = uint2{ half2(w[k0][n], w[k0+1][n]),
    //                                     half2(w[k0+8][n], w[k0+9][n]) }
    // with k0 = 16*ks + 2*(lane&3), n = n0 + 8*nt + (lane>>2)
    uint2* wfrag = (uint2*)s1mem;
#pragma unroll
    for (int q = 0; q < 32; q++) {
        int idx = tid + 128 * q;               // 0..4095
        int ks = idx >> 8;
        int nt = (idx >> 5) & 7;
        int l2 = idx & 31;
        int n = n0 + 8 * nt + (l2 >> 2);
        int k0 = 16 * ks + 2 * (l2 & 3);
        float f0 = __ldg(&w[(size_t)k0 * 256 + n]);
        float f1 = __ldg(&w[(size_t)(k0 + 1) * 256 + n]);
        float f2 = __ldg(&w[(size_t)(k0 + 8) * 256 + n]);
        float f3 = __ldg(&w[(size_t)(k0 + 9) * 256 + n]);
        wfrag[idx] = make_uint2(f2h2(f0, f1), f2h2(f2, f3));
    }
    __syncthreads();

    // ---- mainloop ----
    const int rw = j0 + 32 * wid;
    float acc[2][8][4];
#pragma unroll
    for (int m = 0; m < 2; m++)
#pragma unroll
        for (int nt = 0; nt < 8; nt++)
#pragma unroll
            for (int r = 0; r < 4; r++) acc[m][nt][r] = 0.f;

#pragma unroll
    for (int ks = 0; ks < 16; ks++) {
        const int k0 = 16 * ks + 2 * li;
        uint32_t a[2][4];
#pragma unroll
        for (int m = 0; m < 2; m++) {
            const float* p0 = V + (size_t)(rw + 16 * m + lr) * 256;
            const float* p1 = p0 + 8 * 256;
            float2 x0 = *(const float2*)(p0 + k0);
            float2 x1 = *(const float2*)(p1 + k0);
            float2 x2 = *(const float2*)(p0 + k0 + 8);
            float2 x3 = *(const float2*)(p1 + k0 + 8);
            a[m][0] = f2h2(x0.x, x0.y);
            a[m][1] = f2h2(x1.x, x1.y);
            a[m][2] = f2h2(x2.x, x2.y);
            a[m][3] = f2h2(x3.x, x3.y);
        }
#pragma unroll
        for (int nt = 0; nt < 8; nt++) {
            uint2 bw = wfrag[(ks * 8 + nt) * 32 + l];
            mma_f16(acc[0][nt], a[0][0], a[0][1], a[0][2], a[0][3], bw.x, bw.y);
            mma_f16(acc[1][nt], a[1][0], a[1][1], a[1][2], a[1][3], bw.x, bw.y);
        }
    }

    // ---- epilogue: transpose via per-warp smem tile, write g_B -------------
    // tb layout: [j_local 0..31][n_local 0..63], row stride 66 halves
    __half* tb = (__half*)(s1mem + S1_WFRAG_BYTES + wid * S1_TBUF_BYTES);

#pragma unroll
    for (int m = 0; m < 2; m++) {
#pragma unroll
        for (int nt = 0; nt < 8; nt++) {
            const int jrow = 16 * m + lr;
            const int nloc = 8 * nt + 2 * li;
            __half2 lo = __floats2half2_rn(acc[m][nt][0], acc[m][nt][1]);
            __half2 hi = __floats2half2_rn(acc[m][nt][2], acc[m][nt][3]);
            *(__half2*)&tb[jrow * 66 + nloc] = lo;          // (j, n), (j, n+1)
            *(__half2*)&tb[(jrow + 8) * 66 + nloc] = hi;    // (j+8, n..)
        }
    }
    __syncwarp();

    // g_B slice for this warp: kc = (j0+32*wid)/64, hl = (wid&1)
    const int kc = (j0 + 32 * wid) >> 6;
    const int hl = wid & 1;
#pragma unroll
    for (int nt = 0; nt < 8; nt++) {
        const int nloc = 8 * nt + lr;
        const int jb = 2 * li;
        ushort h[8];
#pragma unroll
        for (int i = 0; i < 2; i++) {       // j offsets {0,1,8,9}, {16,17,24,25}
            h[4 * i + 0] = *(ushort*)&tb[(jb + 16 * i + 0) * 66 + nloc];
            h[4 * i + 1] = *(ushort*)&tb[(jb + 16 * i + 1) * 66 + nloc];
            h[4 * i + 2] = *(ushort*)&tb[(jb + 16 * i + 8) * 66 + nloc];
            h[4 * i + 3] = *(ushort*)&tb[(jb + 16 * i + 9) * 66 + nloc];
        }
        uint4 val;
        val.x = (uint32_t)h[0] | ((uint32_t)h[1] << 16);
        val.y = (uint32_t)h[2] | ((uint32_t)h[3] << 16);
        val.z = (uint32_t)h[4] | ((uint32_t)h[5] << 16);
        val.w = (uint32_t)h[6] | ((uint32_t)h[7] << 16);
        size_t off = (size_t)type * BS_TYPE
                   + (size_t)(blockIdx.y * 8 + nt) * BS_NTILE
                   + (size_t)kc * BS_CHUNK + (size_t)hl * BS_HALF + (size_t)l * 16;
        *(uint4*)&g_B[off] = val;
    }
}

// ---------------- Stage 2: mask-GEMM (exact R4 config + PRMT masks) ---------
// grid 128: bid -> (m_tile = bid>>1, n_half = bid&1). 256 threads, 8 warps.
// Warp wid owns rows [i0 + wid*16, +16). CTA covers 128 output features.

__global__ void __launch_bounds__(256, 1)
stage2_kernel(const int* __restrict__ adj,
              const float* __restrict__ bias,
              float* __restrict__ out) {
    extern __shared__ uint8_t smem[];
    const uint32_t smem_base = smem_u32(smem);

    const int tid = threadIdx.x;
    const int wid = tid >> 5, l = tid & 31;
    const int m_tile = blockIdx.x >> 1;
    const int n_half = blockIdx.x & 1;
    const int i0 = m_tile * 128;
    const int n0 = n_half * 128;
    const int li = l & 3;

    const int rowA = i0 + wid * 16 + (l >> 2);
    const int2* aA = (const int2*)(adj + (size_t)rowA * NROWS);
    const int2* aB = (const int2*)(adj + (size_t)(rowA + 8) * NROWS);

    float acc[16][4];
#pragma unroll
    for (int nt = 0; nt < 16; nt++)
#pragma unroll
        for (int r = 0; r < 4; r++) acc[nt][r] = 0.f;

    // prologue: stage chunks 0..STAGES-2
#pragma unroll
    for (int p = 0; p < STAGES - 1; p++) {
#pragma unroll
        for (int q = 0; q < 12; q++) {
            int idx = tid + 256 * q;                 // 0..3071
            int type = idx >> 10;
            int rem = idx & 1023;
            int nt = rem >> 6;
            int hl = (rem >> 5) & 1;
            int lane = rem & 31;
            const uint8_t* src = g_B + (size_t)type * BS_TYPE
                + (size_t)(n_half * 16 + nt) * BS_NTILE + (size_t)p * BS_CHUNK
                + (size_t)hl * BS_HALF + (size_t)lane * 16;
            cp_async16(smem_base + p * STAGE_BYTES + idx * 16, src);
        }
        CP_COMMIT();
    }

    // preload adj chunk 0
    int2 vA0[4], vA1[4], vB0[4], vB1[4];
#pragma unroll
    for (int s = 0; s < 4; s++) {
        vA0[s] = aA[8 * s + li];
        vA1[s] = aA[8 * s + li + 4];
        vB0[s] = aB[8 * s + li];
        vB1[s] = aB[8 * s + li + 4];
    }

    for (int c = 0; c < NCHUNKS; c++) {
        __syncthreads();   // all warps done consuming the buffer being overwritten
        if (c + STAGES - 1 < NCHUNKS) {
            const int p = c + STAGES - 1;
#pragma unroll
            for (int q = 0; q < 12; q++) {
                int idx = tid + 256 * q;
                int type = idx >> 10;
                int rem = idx & 1023;
                int nt = rem >> 6;
                int hl = (rem >> 5) & 1;
                int lane = rem & 31;
                const uint8_t* src = g_B + (size_t)type * BS_TYPE
                    + (size_t)(n_half * 16 + nt) * BS_NTILE + (size_t)p * BS_CHUNK
                    + (size_t)hl * BS_HALF + (size_t)lane * 16;
                cp_async16(smem_base + (p & 3) * STAGE_BYTES + idx * 16, src);
            }
        }
        CP_COMMIT();

        // pack current adj bytes: pk[ab][s] = [k0, k1, k8, k9]
        uint32_t pkA[4], pkB[4];
#pragma unroll
        for (int s = 0; s < 4; s++) {
            pkA[s] = pack4(vA0[s].x, vA0[s].y, vA1[s].x, vA1[s].y);
            pkB[s] = pack4(vB0[s].x, vB0[s].y, vB1[s].x, vB1[s].y);
        }

        // prefetch adj for next chunk (hidden under this chunk's MMAs)
        if (c + 1 < NCHUNKS) {
            const int base = (c + 1) * 32;
#pragma unroll
            for (int s = 0; s < 4; s++) {
                vA0[s] = aA[base + 8 * s + li];
                vA1[s] = aA[base + 8 * s + li + 4];
                vB0[s] = aB[base + 8 * s + li];
                vB1[s] = aB[base + 8 * s + li + 4];
            }
        }

        CP_WAIT3();
        __syncthreads();   // chunk c fully staged & visible to all warps

        const uint32_t sb = smem_base + (c & 3) * STAGE_BYTES;
#pragma unroll
        for (int t = 0; t < 3; t++) {
            const uint32_t cmp = 0x01010101u * (t + 1);
            uint32_t am[4][4];
#pragma unroll
            for (int s = 0; s < 4; s++) {
                uint32_t eA = __vcmpeq4(pkA[s], cmp) & 0x3C3C3C3Cu;
                uint32_t eB = __vcmpeq4(pkB[s], cmp) & 0x3C3C3C3Cu;
                am[s][0] = prmt(eA, 0u, 0x1404u);   // rowA, {k0,k1}
                am[s][1] = prmt(eB, 0u, 0x1404u);   // rowB
                am[s][2] = prmt(eA, 0u, 0x3424u);   // rowA, {k8,k9}
                am[s][3] = prmt(eB, 0u, 0x3424u);   // rowB
            }
#pragma unroll
            for (int nt = 0; nt < 16; nt++) {
                const uint32_t base = sb + (uint32_t)(((t * 16 + nt) * 2) * 512 + l * 16);
                uint4 u0, u1;
                asm volatile("ld.shared.v4.u32 {%0,%1,%2,%3}, [%4];"
                             : "=r"(u0.x), "=r"(u0.y), "=r"(u0.z), "=r"(u0.w) : "r"(base));
                asm volatile("ld.shared.v4.u32 {%0,%1,%2,%3}, [%4];"
                             : "=r"(u1.x), "=r"(u1.y), "=r"(u1.z), "=r"(u1.w) : "r"(base + 512));
                mma_f16(acc[nt], am[0][0], am[0][1], am[0][2], am[0][3], u0.x, u0.y);
                mma_f16(acc[nt], am[1][0], am[1][1], am[1][2], am[1][3], u0.z, u0.w);
                mma_f16(acc[nt], am[2][0], am[2][1], am[2][2], am[2][3], u1.x, u1.y);
                mma_f16(acc[nt], am[3][0], am[3][1], am[3][2], am[3][3], u1.z, u1.w);
            }
        }
    }

    CP_WAIT0();

    // epilogue: out = acc + bias
#pragma unroll
    for (int nt = 0; nt < 16; nt++) {
        int col = n0 + nt * 8 + 2 * (l & 3);
        float b0 = __ldg(&bias[col]);
        float b1 = __ldg(&bias[col + 1]);
        float2 w0 = make_float2(acc[nt][0] + b0, acc[nt][1] + b1);
        float2 w1 = make_float2(acc[nt][2] + b0, acc[nt][3] + b1);
        *(float2*)&out[(size_t)rowA * FEAT + col] = w0;
        *(float2*)&out[(size_t)(rowA + 8) * FEAT + col] = w1;
    }
}

// ---------------- launch ---------------------------------------------------

extern "C" void kernel_launch(void* const* d_in, const int* in_sizes, int n_in,
                              void* d_out, int out_size) {
    const float* V    = (const float*)d_in[0];
    const int*   adj  = (const int*)d_in[1];
    const float* w1   = (const float*)d_in[2];
    const float* w2   = (const float*)d_in[3];
    const float* w3   = (const float*)d_in[4];
    const float* bias = (const float*)d_in[5];
    float* out = (float*)d_out;

    cudaFuncSetAttribute(stage1_kernel,
                         cudaFuncAttributeMaxDynamicSharedMemorySize, S1_SMEM);
    cudaFuncSetAttribute(stage2_kernel,
                         cudaFuncAttributeMaxDynamicSharedMemorySize, SMEM_TOTAL);

    stage1_kernel<<<dim3(64, 4, 3), 128, S1_SMEM>>>(V, w1, w2, w3);
    stage2_kernel<<<128, 256, SMEM_TOTAL>>>(adj, bias, out);
}